// round 14
// baseline (speedup 1.0000x reference)
#include <cuda_runtime.h>
#include <cuda_fp16.h>
#include <cstdint>
#include <cmath>

// Problem constants
constexpr int Bc  = 2;
constexpr int Sc  = 2048;
constexpr int Ec  = 1024;
constexpr int Hc  = 16;
constexpr int HDc = 64;
constexpr int Mc  = Bc * Sc;        // 4096 rows
constexpr int NQKV = 3 * Ec;        // 3072
constexpr int RHALF = 32;           // rotary pairs per head (ROT=64)
constexpr int GK = 1024;            // K dim of both projection GEMMs

// Scratch (static device globals; no allocation)
__device__ float g_cos[Sc * RHALF];
__device__ float g_sin[Sc * RHALF];

// fp16 buffers
__device__ __half g_x16[(size_t)Mc * Ec];
__device__ __half g_wqkv[(size_t)NQKV * Ec];
__device__ __half g_wout[(size_t)Ec * Ec];
__device__ __half g_ctx16[(size_t)Mc * Ec];

// q/k/v fp16 in [B,H,S,HD] layout (written directly by the QKV GEMM epilogue)
constexpr size_t QKV_ELEMS = (size_t)Bc * Hc * Sc * HDc;
__device__ __half g_q16[QKV_ELEMS];
__device__ __half g_k16[QKV_ELEMS];
__device__ __half g_v16[QKV_ELEMS];

// ---------------------------------------------------------------------------
// Portable (compute_103-safe) tensor-core helpers
// ---------------------------------------------------------------------------
__device__ __forceinline__ uint32_t smem_to_u32(const void* p) {
    uint32_t a;
    asm("{ .reg .u64 t; cvta.to.shared.u64 t, %1; cvt.u32.u64 %0, t; }"
        : "=r"(a) : "l"(p));
    return a;
}
__device__ __forceinline__ void cp16(uint32_t dst, const void* src) {
    asm volatile("cp.async.cg.shared.global [%0], [%1], 16;"
                 :: "r"(dst), "l"(src));
}
__device__ __forceinline__ void cp_commit() {
    asm volatile("cp.async.commit_group;" ::: "memory");
}
__device__ __forceinline__ void ldsm_x4(uint4& r, uint32_t addr) {
    asm volatile("ldmatrix.sync.aligned.m8n8.x4.shared.b16 {%0,%1,%2,%3}, [%4];"
                 : "=r"(r.x), "=r"(r.y), "=r"(r.z), "=r"(r.w) : "r"(addr));
}
__device__ __forceinline__ void ldsm_x4t(uint4& r, uint32_t addr) {
    asm volatile("ldmatrix.sync.aligned.m8n8.x4.trans.shared.b16 {%0,%1,%2,%3}, [%4];"
                 : "=r"(r.x), "=r"(r.y), "=r"(r.z), "=r"(r.w) : "r"(addr));
}
__device__ __forceinline__ void mmah(float* d, const uint4& a, uint32_t b0, uint32_t b1) {
    asm volatile(
        "mma.sync.aligned.m16n8k16.row.col.f32.f16.f16.f32 "
        "{%0,%1,%2,%3}, {%4,%5,%6,%7}, {%8,%9}, {%0,%1,%2,%3};"
        : "+f"(d[0]), "+f"(d[1]), "+f"(d[2]), "+f"(d[3])
        : "r"(a.x), "r"(a.y), "r"(a.z), "r"(a.w), "r"(b0), "r"(b1));
}
__device__ __forceinline__ float ex2f(float x) {
    float r; asm("ex2.approx.f32 %0, %1;" : "=f"(r) : "f"(x)); return r;
}
__device__ __forceinline__ uint32_t packh(float lo, float hi) {
    __half2 t = __floats2half2_rn(lo, hi);
    return *(uint32_t*)&t;
}

// ---------------------------------------------------------------------------
// Prep: fp32->fp16 converts for x / qkv_w / out_w + RoPE table, one launch.
// ---------------------------------------------------------------------------
constexpr int PN1 = Mc * Ec / 4;        // 262144
constexpr int PN2 = NQKV * Ec / 4;      // 786432
constexpr int PN3 = Ec * Ec / 4;        // 262144
constexpr int PTOT = PN1 + PN2 + PN3;   // 1310720

__global__ void prep_kernel(const float* __restrict__ x,
                            const float* __restrict__ qkv_w,
                            const float* __restrict__ out_w) {
    int idx = blockIdx.x * blockDim.x + threadIdx.x;

    if (idx < Sc * RHALF) {
        int s = idx / RHALF;
        int i = idx % RHALF;
        double inv_freq = exp(-(double)(2 * i) / 64.0 * log(10000.0));
        double ang = (double)s * inv_freq;
        g_cos[idx] = (float)cos(ang);
        g_sin[idx] = (float)sin(ang);
    }
    if (idx >= PTOT) return;

    const float* src;
    uint2* dp;
    int i4;
    if (idx < PN1)            { src = x;     dp = (uint2*)g_x16;  i4 = idx; }
    else if (idx < PN1 + PN2) { src = qkv_w; dp = (uint2*)g_wqkv; i4 = idx - PN1; }
    else                      { src = out_w; dp = (uint2*)g_wout; i4 = idx - PN1 - PN2; }

    float4 v = ((const float4*)src)[i4];
    uint2 o;
    o.x = packh(v.x, v.y);
    o.y = packh(v.z, v.w);
    dp[i4] = o;
}

// ---------------------------------------------------------------------------
// Warp-mma fp16 GEMM (round-11/13 proven config): 128x128 CTA tile, BK=64,
// 3-stage cp.async, 2 CTAs/SM, 8 warps (64x32 each). K=1024 -> 16 chunks.
// B fragments loaded as n-tile PAIRS via ldmatrix.x4.
// MODE 0: C fp32 = A@B^T + bias (out projection)
// MODE 1: QKV epilogue — bias + RoPE, write q/k/v fp16 in [B,H,S,HD].
// ---------------------------------------------------------------------------
constexpr int GQ_PITCH = 144;
constexpr int GQ_TILE  = 128 * GQ_PITCH;        // 18432
constexpr int GQ_B     = GQ_TILE;
constexpr int GQ_STAGE = 2 * GQ_TILE;           // 36864
constexpr int GQ_SMEM  = 3 * GQ_STAGE;          // 110592

template <int MODE>
__global__ __launch_bounds__(256, 2) void gemm_mma_f16(
    const __half* __restrict__ A16, const __half* __restrict__ B16,
    const float* __restrict__ bias, float* __restrict__ C, int Ndim)
{
    extern __shared__ char smg[];
    const uint32_t sb = smem_to_u32(smg);
    const int tid = threadIdx.x;
    const int lane = tid & 31;
    const int wid = tid >> 5;
    const int rowBase = blockIdx.y * 128;
    const int colBase = blockIdx.x * 128;
    const int wm = (wid >> 2) * 64;
    const int wn = (wid & 3) * 32;

    float acc[4][4][4];
#pragma unroll
    for (int mi = 0; mi < 4; mi++)
#pragma unroll
        for (int ni = 0; ni < 4; ni++)
#pragma unroll
            for (int e = 0; e < 4; e++) acc[mi][ni][e] = 0.f;

    auto issue = [&](int k) {
        const int k0 = k * 64;
        const uint32_t dst = sb + (uint32_t)(k % 3) * GQ_STAGE;
#pragma unroll
        for (int u = 0; u < 4; u++) {
            int lin = u * 256 + tid;
            int r = lin >> 3, seg = lin & 7;
            uint32_t so = r * GQ_PITCH + seg * 16;
            cp16(dst + so, A16 + (size_t)(rowBase + r) * GK + k0 + seg * 8);
            cp16(dst + GQ_B + so, B16 + (size_t)(colBase + r) * GK + k0 + seg * 8);
        }
        cp_commit();
    };

    issue(0);
    issue(1);
    for (int k = 0; k < 16; k++) {
        if (k < 15) asm volatile("cp.async.wait_group 1;" ::: "memory");
        else        asm volatile("cp.async.wait_group 0;" ::: "memory");
        __syncthreads();
        if (k + 2 < 16) issue(k + 2);   // stage (k+2)%3 — not read now or next

        const uint32_t St = sb + (uint32_t)(k % 3) * GQ_STAGE;
#pragma unroll
        for (int ks = 0; ks < 4; ks++) {
            uint4 a[4];
            uint4 bb[2];
            const uint32_t aro = (wm + (lane & 15)) * GQ_PITCH
                               + (ks * 16 + (lane >> 4) * 8) * 2;
#pragma unroll
            for (int mi = 0; mi < 4; mi++)
                ldsm_x4(a[mi], St + aro + mi * 16 * GQ_PITCH);
            const uint32_t bro = (wn + (lane & 7) + (lane >> 4) * 8) * GQ_PITCH
                               + (ks * 16 + ((lane >> 3) & 1) * 8) * 2;
#pragma unroll
            for (int nj = 0; nj < 2; nj++)
                ldsm_x4(bb[nj], St + GQ_B + bro + nj * 16 * GQ_PITCH);
#pragma unroll
            for (int mi = 0; mi < 4; mi++) {
                mmah(acc[mi][0], a[mi], bb[0].x, bb[0].y);
                mmah(acc[mi][1], a[mi], bb[0].z, bb[0].w);
                mmah(acc[mi][2], a[mi], bb[1].x, bb[1].y);
                mmah(acc[mi][3], a[mi], bb[1].z, bb[1].w);
            }
        }
    }

#pragma unroll
    for (int mi = 0; mi < 4; mi++) {
#pragma unroll
        for (int ni = 0; ni < 4; ni++) {
            int r0 = rowBase + wm + mi * 16 + (lane >> 2);
            int col = colBase + wn + ni * 8 + (lane & 3) * 2;
            float b0 = bias[col], b1 = bias[col + 1];
            float v00 = acc[mi][ni][0] + b0, v01 = acc[mi][ni][1] + b1;   // row r0
            float v10 = acc[mi][ni][2] + b0, v11 = acc[mi][ni][3] + b1;   // row r0+8

            if (MODE == 0) {
                *(float2*)&C[(size_t)r0 * Ndim + col] = make_float2(v00, v01);
                *(float2*)&C[(size_t)(r0 + 8) * Ndim + col] = make_float2(v10, v11);
            } else {
                int seg = col >> 10;             // 0=q 1=k 2=v
                int h = (col >> 6) & 15;
                int d = col & 63;
                int i = d >> 1;
                __half* dstBuf = (seg == 0) ? g_q16 : (seg == 1) ? g_k16 : g_v16;
#pragma unroll
                for (int rr = 0; rr < 2; rr++) {
                    int r = r0 + rr * 8;
                    float va = rr ? v10 : v00;
                    float vb = rr ? v11 : v01;
                    int bb2 = r >> 11;
                    int s = r & 2047;
                    size_t dst = (((size_t)(bb2 * Hc + h)) * Sc + s) * HDc + d;
                    if (seg == 2) {
                        *(__half2*)&dstBuf[dst] = __floats2half2_rn(va, vb);
                    } else {
                        float c  = g_cos[s * RHALF + i];
                        float sn = g_sin[s * RHALF + i];
                        *(__half2*)&dstBuf[dst] =
                            __floats2half2_rn(va * c - vb * sn, vb * c + va * sn);
                    }
                }
            }
        }
    }
}

// ---------------------------------------------------------------------------
// Tensor-core flash attention, fp16 operands, fp32 accum, no-max softmax.
// 128 q-rows/CTA, 64-key tiles, 8 warps, HD=64.
// 3-STAGE KV ring -> single __syncthreads per iteration. ~74.5 KB smem.
// ---------------------------------------------------------------------------
constexpr int AT_PITCH = 144;
constexpr int AT_Q   = 0;
constexpr int AT_KV  = 128 * AT_PITCH;            // 18432 (Q tile size)
constexpr int AT_V   = 64 * AT_PITCH;             // V offset within stage
constexpr int AT_KVSTG = 2 * 64 * AT_PITCH;       // 18432 per stage (K+V)
constexpr int AT_MSK = AT_KV + 3 * AT_KVSTG;      // 73728
constexpr int AT_SMEM = AT_MSK + 3 * 64 * 4;      // 74496

__global__ __launch_bounds__(256) void attn_mma_kernel(const int* __restrict__ mask)
{
    extern __shared__ char smA[];
    const uint32_t sb = smem_to_u32(smA);
    float* smask = (float*)(smA + AT_MSK);

    const int tid = threadIdx.x;
    const int lane = tid & 31;
    const int wid = tid >> 5;
    const int bh = blockIdx.y;
    const int b = bh >> 4, h = bh & 15;
    const int q0 = blockIdx.x * 128;

    const size_t base = (size_t)bh * Sc * HDc;
    const __half* Qg = g_q16 + base + (size_t)q0 * HDc;
    const __half* Kg = g_k16 + base;
    const __half* Vg = g_v16 + base;
    const int* mg = mask + b * Sc;

#pragma unroll
    for (int u = 0; u < 4; u++) {
        int lin = u * 256 + tid;
        int r = lin >> 3, seg = lin & 7;
        cp16(sb + AT_Q + r * AT_PITCH + seg * 16, Qg + (size_t)r * HDc + seg * 8);
    }

    auto issueKV = [&](int it) {
        const int stg = it % 3;
        const uint32_t dst = sb + AT_KV + (uint32_t)stg * AT_KVSTG;
        const size_t koff = (size_t)it * 64 * HDc;
#pragma unroll
        for (int u = 0; u < 2; u++) {
            int lin = u * 256 + tid;
            int r = lin >> 3, seg = lin & 7;
            size_t off = koff + (size_t)r * HDc + seg * 8;
            uint32_t so = r * AT_PITCH + seg * 16;
            cp16(dst + so, Kg + off);
            cp16(dst + AT_V + so, Vg + off);
        }
        if (tid < 64) smask[stg * 64 + tid] = mg[it * 64 + tid] ? 0.f : -1e30f;
        cp_commit();
    };

    issueKV(0);
    issueKV(1);

    float accO[8][4];
#pragma unroll
    for (int nd = 0; nd < 8; nd++)
#pragma unroll
        for (int e = 0; e < 4; e++) accO[nd][e] = 0.f;
    float l0 = 0.f, l1 = 0.f;
    const float SC2 = 0.125f * 1.4426950408889634f;   // scale * log2(e)

    uint4 qf[4];
    bool qloaded = false;

    for (int it = 0; it < 32; it++) {
        if (it < 31) asm volatile("cp.async.wait_group 1;" ::: "memory");
        else         asm volatile("cp.async.wait_group 0;" ::: "memory");
        __syncthreads();
        if (it + 2 < 32) issueKV(it + 2);   // stage (it+2)%3 — not read now/next

        if (!qloaded) {
            // Q arrived with the first group (same commit as KV0)
#pragma unroll
            for (int ks = 0; ks < 4; ks++) {
                uint32_t ro = (wid * 16 + (lane & 15)) * AT_PITCH
                            + (ks * 16 + (lane >> 4) * 8) * 2;
                ldsm_x4(qf[ks], sb + AT_Q + ro);
            }
            qloaded = true;
        }

        const uint32_t Kb = sb + AT_KV + (uint32_t)(it % 3) * AT_KVSTG;
        const int mbuf = (it % 3) * 64;

        // ---- S = Q K^T (key-tile pairs via ldsm_x4) ----
        float s[8][4];
#pragma unroll
        for (int ni = 0; ni < 8; ni++)
#pragma unroll
            for (int e = 0; e < 4; e++) s[ni][e] = 0.f;
#pragma unroll
        for (int ks = 0; ks < 4; ks++) {
            uint4 bk[4];
            uint32_t ro = ((lane & 7) + (lane >> 4) * 8) * AT_PITCH
                        + (ks * 16 + ((lane >> 3) & 1) * 8) * 2;
#pragma unroll
            for (int nj = 0; nj < 4; nj++)
                ldsm_x4(bk[nj], Kb + ro + nj * 16 * AT_PITCH);
#pragma unroll
            for (int nj = 0; nj < 4; nj++) {
                mmah(s[2 * nj],     qf[ks], bk[nj].x, bk[nj].y);
                mmah(s[2 * nj + 1], qf[ks], bk[nj].z, bk[nj].w);
            }
        }

        // ---- p = ex2(s*SC2 + mask), thread-local l accumulation ----
#pragma unroll
        for (int ni = 0; ni < 8; ni++) {
            float mb0 = smask[mbuf + ni * 8 + (lane & 3) * 2];
            float mb1 = smask[mbuf + ni * 8 + (lane & 3) * 2 + 1];
            s[ni][0] = ex2f(fmaf(s[ni][0], SC2, mb0));
            s[ni][1] = ex2f(fmaf(s[ni][1], SC2, mb1));
            s[ni][2] = ex2f(fmaf(s[ni][2], SC2, mb0));
            s[ni][3] = ex2f(fmaf(s[ni][3], SC2, mb1));
            l0 += s[ni][0] + s[ni][1];
            l1 += s[ni][2] + s[ni][3];
        }

        // ---- P fragments (fp16) from S accumulators ----
        uint4 ap[4];
#pragma unroll
        for (int ks2 = 0; ks2 < 4; ks2++) {
            const float* p0 = s[2 * ks2];
            const float* p1 = s[2 * ks2 + 1];
            ap[ks2].x = packh(p0[0], p0[1]);
            ap[ks2].y = packh(p0[2], p0[3]);
            ap[ks2].z = packh(p1[0], p1[1]);
            ap[ks2].w = packh(p1[2], p1[3]);
        }

        // ---- O += P V (d-tile pairs via ldsm_x4.trans) ----
#pragma unroll
        for (int ks2 = 0; ks2 < 4; ks2++) {
            uint4 bv[4];
            uint32_t rbase = (ks2 * 16 + (lane & 15)) * AT_PITCH + (lane >> 4) * 16;
#pragma unroll
            for (int nd2 = 0; nd2 < 4; nd2++)
                ldsm_x4t(bv[nd2], Kb + AT_V + rbase + nd2 * 32);
#pragma unroll
            for (int nd2 = 0; nd2 < 4; nd2++) {
                mmah(accO[2 * nd2],     ap[ks2], bv[nd2].x, bv[nd2].y);
                mmah(accO[2 * nd2 + 1], ap[ks2], bv[nd2].z, bv[nd2].w);
            }
        }
    }

    // ---- one-time row-sum reduction (quad lanes share a row) ----
    l0 += __shfl_xor_sync(0xffffffffu, l0, 1);
    l0 += __shfl_xor_sync(0xffffffffu, l0, 2);
    l1 += __shfl_xor_sync(0xffffffffu, l1, 1);
    l1 += __shfl_xor_sync(0xffffffffu, l1, 2);

    float inv0 = 1.f / l0, inv1 = 1.f / l1;
    int r0 = q0 + wid * 16 + (lane >> 2);
    int colb = h * HDc + (lane & 3) * 2;
#pragma unroll
    for (int nd = 0; nd < 8; nd++) {
        float c00 = accO[nd][0] * inv0, c01 = accO[nd][1] * inv0;
        float c10 = accO[nd][2] * inv1, c11 = accO[nd][3] * inv1;
        size_t i0 = (size_t)(b * Sc + r0) * Ec + colb + nd * 8;
        size_t i1 = (size_t)(b * Sc + r0 + 8) * Ec + colb + nd * 8;
        *(__half2*)&g_ctx16[i0] = __floats2half2_rn(c00, c01);
        *(__half2*)&g_ctx16[i1] = __floats2half2_rn(c10, c11);
    }
}

// ---------------------------------------------------------------------------
extern "C" void kernel_launch(void* const* d_in, const int* in_sizes, int n_in,
                              void* d_out, int out_size)
{
    const float* x     = (const float*)d_in[0];
    const int*   mask  = (const int*)d_in[1];
    const float* qkv_w = (const float*)d_in[2];
    const float* qkv_b = (const float*)d_in[3];
    const float* out_w = (const float*)d_in[4];
    const float* out_b = (const float*)d_in[5];
    float* out = (float*)d_out;

    __half *x16, *w16, *ow16, *c16;
    cudaGetSymbolAddress((void**)&x16,  g_x16);
    cudaGetSymbolAddress((void**)&w16,  g_wqkv);
    cudaGetSymbolAddress((void**)&ow16, g_wout);
    cudaGetSymbolAddress((void**)&c16,  g_ctx16);

    cudaFuncSetAttribute(gemm_mma_f16<0>,
                         cudaFuncAttributeMaxDynamicSharedMemorySize, GQ_SMEM);
    cudaFuncSetAttribute(gemm_mma_f16<1>,
                         cudaFuncAttributeMaxDynamicSharedMemorySize, GQ_SMEM);
    cudaFuncSetAttribute(attn_mma_kernel,
                         cudaFuncAttributeMaxDynamicSharedMemorySize, AT_SMEM);

    // 1. Converts + RoPE table (one launch)
    prep_kernel<<<(PTOT + 255) / 256, 256>>>(x, qkv_w, out_w);

    // 2. QKV projection with fused bias+RoPE epilogue -> q/k/v fp16 [B,H,S,HD]
    gemm_mma_f16<1><<<dim3(NQKV / 128, Mc / 128), 256, GQ_SMEM>>>(
        x16, w16, qkv_b, nullptr, NQKV);

    // 3. Tensor-core flash attention (no-max softmax, 3-stage ring) -> ctx fp16
    attn_mma_kernel<<<dim3(Sc / 128, Bc * Hc), 256, AT_SMEM>>>(mask);

    // 4. Output projection -> fp32 out
    gemm_mma_f16<0><<<dim3(Ec / 128, Mc / 128), 256, GQ_SMEM>>>(
        c16, ow16, out_b, out, Ec);
}

// round 15
// speedup vs baseline: 1.0214x; 1.0214x over previous
#include <cuda_runtime.h>
#include <cuda_fp16.h>
#include <cstdint>
#include <cmath>

// Problem constants
constexpr int Bc  = 2;
constexpr int Sc  = 2048;
constexpr int Ec  = 1024;
constexpr int Hc  = 16;
constexpr int HDc = 64;
constexpr int Mc  = Bc * Sc;        // 4096 rows
constexpr int NQKV = 3 * Ec;        // 3072
constexpr int RHALF = 32;           // rotary pairs per head (ROT=64)
constexpr int GK = 1024;            // K dim of both projection GEMMs

// Scratch (static device globals; no allocation)
__device__ float g_cos[Sc * RHALF];
__device__ float g_sin[Sc * RHALF];

// fp16 buffers
__device__ __half g_x16[(size_t)Mc * Ec];
__device__ __half g_wqkv[(size_t)NQKV * Ec];
__device__ __half g_wout[(size_t)Ec * Ec];
__device__ __half g_ctx16[(size_t)Mc * Ec];

// q/k/v fp16 in [B,H,S,HD] layout (written directly by the QKV GEMM epilogue)
constexpr size_t QKV_ELEMS = (size_t)Bc * Hc * Sc * HDc;
__device__ __half g_q16[QKV_ELEMS];
__device__ __half g_k16[QKV_ELEMS];
__device__ __half g_v16[QKV_ELEMS];

// ---------------------------------------------------------------------------
// Portable (compute_103-safe) tensor-core helpers
// ---------------------------------------------------------------------------
__device__ __forceinline__ uint32_t smem_to_u32(const void* p) {
    uint32_t a;
    asm("{ .reg .u64 t; cvta.to.shared.u64 t, %1; cvt.u32.u64 %0, t; }"
        : "=r"(a) : "l"(p));
    return a;
}
__device__ __forceinline__ void cp16(uint32_t dst, const void* src) {
    asm volatile("cp.async.cg.shared.global [%0], [%1], 16;"
                 :: "r"(dst), "l"(src));
}
__device__ __forceinline__ void cp_commit() {
    asm volatile("cp.async.commit_group;" ::: "memory");
}
__device__ __forceinline__ void ldsm_x4(uint4& r, uint32_t addr) {
    asm volatile("ldmatrix.sync.aligned.m8n8.x4.shared.b16 {%0,%1,%2,%3}, [%4];"
                 : "=r"(r.x), "=r"(r.y), "=r"(r.z), "=r"(r.w) : "r"(addr));
}
__device__ __forceinline__ void ldsm_x4t(uint4& r, uint32_t addr) {
    asm volatile("ldmatrix.sync.aligned.m8n8.x4.trans.shared.b16 {%0,%1,%2,%3}, [%4];"
                 : "=r"(r.x), "=r"(r.y), "=r"(r.z), "=r"(r.w) : "r"(addr));
}
__device__ __forceinline__ void mmah(float* d, const uint4& a, uint32_t b0, uint32_t b1) {
    asm volatile(
        "mma.sync.aligned.m16n8k16.row.col.f32.f16.f16.f32 "
        "{%0,%1,%2,%3}, {%4,%5,%6,%7}, {%8,%9}, {%0,%1,%2,%3};"
        : "+f"(d[0]), "+f"(d[1]), "+f"(d[2]), "+f"(d[3])
        : "r"(a.x), "r"(a.y), "r"(a.z), "r"(a.w), "r"(b0), "r"(b1));
}
__device__ __forceinline__ float ex2f(float x) {
    float r; asm("ex2.approx.f32 %0, %1;" : "=f"(r) : "f"(x)); return r;
}
__device__ __forceinline__ uint32_t packh(float lo, float hi) {
    __half2 t = __floats2half2_rn(lo, hi);
    return *(uint32_t*)&t;
}

// ---------------------------------------------------------------------------
// Prep: fp32->fp16 converts for x / qkv_w / out_w + RoPE table, one launch.
// Coalesced uint2 stores (one 8B store per float4 read).
// ---------------------------------------------------------------------------
constexpr int PN1 = Mc * Ec / 4;        // 262144
constexpr int PN2 = NQKV * Ec / 4;      // 786432
constexpr int PN3 = Ec * Ec / 4;        // 262144
constexpr int PTOT = PN1 + PN2 + PN3;   // 1310720

__global__ void prep_kernel(const float* __restrict__ x,
                            const float* __restrict__ qkv_w,
                            const float* __restrict__ out_w) {
    int idx = blockIdx.x * blockDim.x + threadIdx.x;

    if (idx < Sc * RHALF) {
        int s = idx / RHALF;
        int i = idx % RHALF;
        double inv_freq = exp(-(double)(2 * i) / 64.0 * log(10000.0));
        double ang = (double)s * inv_freq;
        g_cos[idx] = (float)cos(ang);
        g_sin[idx] = (float)sin(ang);
    }
    if (idx >= PTOT) return;

    const float* src;
    uint2* dp;
    int i4;
    if (idx < PN1)            { src = x;     dp = (uint2*)g_x16;  i4 = idx; }
    else if (idx < PN1 + PN2) { src = qkv_w; dp = (uint2*)g_wqkv; i4 = idx - PN1; }
    else                      { src = out_w; dp = (uint2*)g_wout; i4 = idx - PN1 - PN2; }

    float4 v = ((const float4*)src)[i4];
    uint2 o;
    o.x = packh(v.x, v.y);
    o.y = packh(v.z, v.w);
    dp[i4] = o;
}

// ---------------------------------------------------------------------------
// Warp-mma fp16 GEMM (round-11/13 proven config): 128x128 CTA tile, BK=64,
// 3-stage cp.async, 2 CTAs/SM, 8 warps (64x32 each). K=1024 -> 16 chunks.
// B fragments loaded as n-tile PAIRS via ldmatrix.x4.
// MODE 0: C fp32 = A@B^T + bias (out projection)
// MODE 1: QKV epilogue — bias + RoPE, write q/k/v fp16 in [B,H,S,HD].
// ---------------------------------------------------------------------------
constexpr int GQ_PITCH = 144;
constexpr int GQ_TILE  = 128 * GQ_PITCH;        // 18432
constexpr int GQ_B     = GQ_TILE;
constexpr int GQ_STAGE = 2 * GQ_TILE;           // 36864
constexpr int GQ_SMEM  = 3 * GQ_STAGE;          // 110592

template <int MODE>
__global__ __launch_bounds__(256, 2) void gemm_mma_f16(
    const __half* __restrict__ A16, const __half* __restrict__ B16,
    const float* __restrict__ bias, float* __restrict__ C, int Ndim)
{
    extern __shared__ char smg[];
    const uint32_t sb = smem_to_u32(smg);
    const int tid = threadIdx.x;
    const int lane = tid & 31;
    const int wid = tid >> 5;
    const int rowBase = blockIdx.y * 128;
    const int colBase = blockIdx.x * 128;
    const int wm = (wid >> 2) * 64;
    const int wn = (wid & 3) * 32;

    float acc[4][4][4];
#pragma unroll
    for (int mi = 0; mi < 4; mi++)
#pragma unroll
        for (int ni = 0; ni < 4; ni++)
#pragma unroll
            for (int e = 0; e < 4; e++) acc[mi][ni][e] = 0.f;

    auto issue = [&](int k) {
        const int k0 = k * 64;
        const uint32_t dst = sb + (uint32_t)(k % 3) * GQ_STAGE;
#pragma unroll
        for (int u = 0; u < 4; u++) {
            int lin = u * 256 + tid;
            int r = lin >> 3, seg = lin & 7;
            uint32_t so = r * GQ_PITCH + seg * 16;
            cp16(dst + so, A16 + (size_t)(rowBase + r) * GK + k0 + seg * 8);
            cp16(dst + GQ_B + so, B16 + (size_t)(colBase + r) * GK + k0 + seg * 8);
        }
        cp_commit();
    };

    issue(0);
    issue(1);
    for (int k = 0; k < 16; k++) {
        if (k < 15) asm volatile("cp.async.wait_group 1;" ::: "memory");
        else        asm volatile("cp.async.wait_group 0;" ::: "memory");
        __syncthreads();
        if (k + 2 < 16) issue(k + 2);   // stage (k+2)%3 — not read now or next

        const uint32_t St = sb + (uint32_t)(k % 3) * GQ_STAGE;
#pragma unroll
        for (int ks = 0; ks < 4; ks++) {
            uint4 a[4];
            uint4 bb[2];
            const uint32_t aro = (wm + (lane & 15)) * GQ_PITCH
                               + (ks * 16 + (lane >> 4) * 8) * 2;
#pragma unroll
            for (int mi = 0; mi < 4; mi++)
                ldsm_x4(a[mi], St + aro + mi * 16 * GQ_PITCH);
            const uint32_t bro = (wn + (lane & 7) + (lane >> 4) * 8) * GQ_PITCH
                               + (ks * 16 + ((lane >> 3) & 1) * 8) * 2;
#pragma unroll
            for (int nj = 0; nj < 2; nj++)
                ldsm_x4(bb[nj], St + GQ_B + bro + nj * 16 * GQ_PITCH);
#pragma unroll
            for (int mi = 0; mi < 4; mi++) {
                mmah(acc[mi][0], a[mi], bb[0].x, bb[0].y);
                mmah(acc[mi][1], a[mi], bb[0].z, bb[0].w);
                mmah(acc[mi][2], a[mi], bb[1].x, bb[1].y);
                mmah(acc[mi][3], a[mi], bb[1].z, bb[1].w);
            }
        }
    }

#pragma unroll
    for (int mi = 0; mi < 4; mi++) {
#pragma unroll
        for (int ni = 0; ni < 4; ni++) {
            int r0 = rowBase + wm + mi * 16 + (lane >> 2);
            int col = colBase + wn + ni * 8 + (lane & 3) * 2;
            float b0 = bias[col], b1 = bias[col + 1];
            float v00 = acc[mi][ni][0] + b0, v01 = acc[mi][ni][1] + b1;   // row r0
            float v10 = acc[mi][ni][2] + b0, v11 = acc[mi][ni][3] + b1;   // row r0+8

            if (MODE == 0) {
                *(float2*)&C[(size_t)r0 * Ndim + col] = make_float2(v00, v01);
                *(float2*)&C[(size_t)(r0 + 8) * Ndim + col] = make_float2(v10, v11);
            } else {
                int seg = col >> 10;             // 0=q 1=k 2=v
                int h = (col >> 6) & 15;
                int d = col & 63;
                int i = d >> 1;
                __half* dstBuf = (seg == 0) ? g_q16 : (seg == 1) ? g_k16 : g_v16;
#pragma unroll
                for (int rr = 0; rr < 2; rr++) {
                    int r = r0 + rr * 8;
                    float va = rr ? v10 : v00;
                    float vb = rr ? v11 : v01;
                    int bb2 = r >> 11;
                    int s = r & 2047;
                    size_t dst = (((size_t)(bb2 * Hc + h)) * Sc + s) * HDc + d;
                    if (seg == 2) {
                        *(__half2*)&dstBuf[dst] = __floats2half2_rn(va, vb);
                    } else {
                        float c  = g_cos[s * RHALF + i];
                        float sn = g_sin[s * RHALF + i];
                        *(__half2*)&dstBuf[dst] =
                            __floats2half2_rn(va * c - vb * sn, vb * c + va * sn);
                    }
                }
            }
        }
    }
}

// ---------------------------------------------------------------------------
// Tensor-core flash attention (round-13 proven): fp16 operands, fp32 accum,
// NO-MAX softmax (scores bounded), 2-buffer KV ring.
// 128 q-rows/CTA, 64-key tiles, 8 warps, HD=64. ~55 KB smem.
// ---------------------------------------------------------------------------
constexpr int AT_PITCH = 144;
constexpr int AT_Q   = 0;
constexpr int AT_KV  = 128 * AT_PITCH;            // 18432
constexpr int AT_V   = 64 * AT_PITCH;             // offset within buffer
constexpr int AT_KVBUF = 2 * 64 * AT_PITCH;       // 18432 per buffer
constexpr int AT_MSK = AT_KV + 2 * AT_KVBUF;      // 55296
constexpr int AT_SMEM = AT_MSK + 2 * 64 * 4;      // 55808

__global__ __launch_bounds__(256) void attn_mma_kernel(const int* __restrict__ mask)
{
    extern __shared__ char smA[];
    const uint32_t sb = smem_to_u32(smA);
    float* smask = (float*)(smA + AT_MSK);

    const int tid = threadIdx.x;
    const int lane = tid & 31;
    const int wid = tid >> 5;
    const int bh = blockIdx.y;
    const int b = bh >> 4, h = bh & 15;
    const int q0 = blockIdx.x * 128;

    const size_t base = (size_t)bh * Sc * HDc;
    const __half* Qg = g_q16 + base + (size_t)q0 * HDc;
    const __half* Kg = g_k16 + base;
    const __half* Vg = g_v16 + base;
    const int* mg = mask + b * Sc;

#pragma unroll
    for (int u = 0; u < 4; u++) {
        int lin = u * 256 + tid;
        int r = lin >> 3, seg = lin & 7;
        cp16(sb + AT_Q + r * AT_PITCH + seg * 16, Qg + (size_t)r * HDc + seg * 8);
    }

    auto issueKV = [&](int it) {
        const uint32_t dst = sb + AT_KV + (uint32_t)(it & 1) * AT_KVBUF;
        const size_t koff = (size_t)it * 64 * HDc;
#pragma unroll
        for (int u = 0; u < 2; u++) {
            int lin = u * 256 + tid;
            int r = lin >> 3, seg = lin & 7;
            size_t off = koff + (size_t)r * HDc + seg * 8;
            uint32_t so = r * AT_PITCH + seg * 16;
            cp16(dst + so, Kg + off);
            cp16(dst + AT_V + so, Vg + off);
        }
        if (tid < 64) smask[(it & 1) * 64 + tid] = mg[it * 64 + tid] ? 0.f : -1e30f;
        cp_commit();
    };

    issueKV(0);
    issueKV(1);
    asm volatile("cp.async.wait_group 1;" ::: "memory");
    __syncthreads();

    uint4 qf[4];
#pragma unroll
    for (int ks = 0; ks < 4; ks++) {
        uint32_t ro = (wid * 16 + (lane & 15)) * AT_PITCH + (ks * 16 + (lane >> 4) * 8) * 2;
        ldsm_x4(qf[ks], sb + AT_Q + ro);
    }

    float accO[8][4];
#pragma unroll
    for (int nd = 0; nd < 8; nd++)
#pragma unroll
        for (int e = 0; e < 4; e++) accO[nd][e] = 0.f;
    float l0 = 0.f, l1 = 0.f;
    const float SC2 = 0.125f * 1.4426950408889634f;   // scale * log2(e)

    for (int it = 0; it < 32; it++) {
        if (it > 0) {
            if (it == 31) asm volatile("cp.async.wait_group 0;" ::: "memory");
            else          asm volatile("cp.async.wait_group 1;" ::: "memory");
            __syncthreads();
        }
        const uint32_t Kb = sb + AT_KV + (uint32_t)(it & 1) * AT_KVBUF;
        const int mbuf = (it & 1) * 64;

        // ---- S = Q K^T (key-tile pairs via ldsm_x4) ----
        float s[8][4];
#pragma unroll
        for (int ni = 0; ni < 8; ni++)
#pragma unroll
            for (int e = 0; e < 4; e++) s[ni][e] = 0.f;
#pragma unroll
        for (int ks = 0; ks < 4; ks++) {
            uint4 bk[4];
            uint32_t ro = ((lane & 7) + (lane >> 4) * 8) * AT_PITCH
                        + (ks * 16 + ((lane >> 3) & 1) * 8) * 2;
#pragma unroll
            for (int nj = 0; nj < 4; nj++)
                ldsm_x4(bk[nj], Kb + ro + nj * 16 * AT_PITCH);
#pragma unroll
            for (int nj = 0; nj < 4; nj++) {
                mmah(s[2 * nj],     qf[ks], bk[nj].x, bk[nj].y);
                mmah(s[2 * nj + 1], qf[ks], bk[nj].z, bk[nj].w);
            }
        }

        // ---- p = ex2(s*SC2 + mask), thread-local l accumulation ----
#pragma unroll
        for (int ni = 0; ni < 8; ni++) {
            float mb0 = smask[mbuf + ni * 8 + (lane & 3) * 2];
            float mb1 = smask[mbuf + ni * 8 + (lane & 3) * 2 + 1];
            s[ni][0] = ex2f(fmaf(s[ni][0], SC2, mb0));
            s[ni][1] = ex2f(fmaf(s[ni][1], SC2, mb1));
            s[ni][2] = ex2f(fmaf(s[ni][2], SC2, mb0));
            s[ni][3] = ex2f(fmaf(s[ni][3], SC2, mb1));
            l0 += s[ni][0] + s[ni][1];
            l1 += s[ni][2] + s[ni][3];
        }

        // ---- P fragments (fp16) from S accumulators ----
        uint4 ap[4];
#pragma unroll
        for (int ks2 = 0; ks2 < 4; ks2++) {
            const float* p0 = s[2 * ks2];
            const float* p1 = s[2 * ks2 + 1];
            ap[ks2].x = packh(p0[0], p0[1]);
            ap[ks2].y = packh(p0[2], p0[3]);
            ap[ks2].z = packh(p1[0], p1[1]);
            ap[ks2].w = packh(p1[2], p1[3]);
        }

        // ---- O += P V (d-tile pairs via ldsm_x4.trans) ----
#pragma unroll
        for (int ks2 = 0; ks2 < 4; ks2++) {
            uint4 bv[4];
            uint32_t rbase = (ks2 * 16 + (lane & 15)) * AT_PITCH + (lane >> 4) * 16;
#pragma unroll
            for (int nd2 = 0; nd2 < 4; nd2++)
                ldsm_x4t(bv[nd2], Kb + AT_V + rbase + nd2 * 32);
#pragma unroll
            for (int nd2 = 0; nd2 < 4; nd2++) {
                mmah(accO[2 * nd2],     ap[ks2], bv[nd2].x, bv[nd2].y);
                mmah(accO[2 * nd2 + 1], ap[ks2], bv[nd2].z, bv[nd2].w);
            }
        }

        __syncthreads();
        if (it + 2 < 32) issueKV(it + 2);
    }

    // ---- one-time row-sum reduction (quad lanes share a row) ----
    l0 += __shfl_xor_sync(0xffffffffu, l0, 1);
    l0 += __shfl_xor_sync(0xffffffffu, l0, 2);
    l1 += __shfl_xor_sync(0xffffffffu, l1, 1);
    l1 += __shfl_xor_sync(0xffffffffu, l1, 2);

    float inv0 = 1.f / l0, inv1 = 1.f / l1;
    int r0 = q0 + wid * 16 + (lane >> 2);
    int colb = h * HDc + (lane & 3) * 2;
#pragma unroll
    for (int nd = 0; nd < 8; nd++) {
        float c00 = accO[nd][0] * inv0, c01 = accO[nd][1] * inv0;
        float c10 = accO[nd][2] * inv1, c11 = accO[nd][3] * inv1;
        size_t i0 = (size_t)(b * Sc + r0) * Ec + colb + nd * 8;
        size_t i1 = (size_t)(b * Sc + r0 + 8) * Ec + colb + nd * 8;
        *(__half2*)&g_ctx16[i0] = __floats2half2_rn(c00, c01);
        *(__half2*)&g_ctx16[i1] = __floats2half2_rn(c10, c11);
    }
}

// ---------------------------------------------------------------------------
extern "C" void kernel_launch(void* const* d_in, const int* in_sizes, int n_in,
                              void* d_out, int out_size)
{
    const float* x     = (const float*)d_in[0];
    const int*   mask  = (const int*)d_in[1];
    const float* qkv_w = (const float*)d_in[2];
    const float* qkv_b = (const float*)d_in[3];
    const float* out_w = (const float*)d_in[4];
    const float* out_b = (const float*)d_in[5];
    float* out = (float*)d_out;

    __half *x16, *w16, *ow16, *c16;
    cudaGetSymbolAddress((void**)&x16,  g_x16);
    cudaGetSymbolAddress((void**)&w16,  g_wqkv);
    cudaGetSymbolAddress((void**)&ow16, g_wout);
    cudaGetSymbolAddress((void**)&c16,  g_ctx16);

    cudaFuncSetAttribute(gemm_mma_f16<0>,
                         cudaFuncAttributeMaxDynamicSharedMemorySize, GQ_SMEM);
    cudaFuncSetAttribute(gemm_mma_f16<1>,
                         cudaFuncAttributeMaxDynamicSharedMemorySize, GQ_SMEM);
    cudaFuncSetAttribute(attn_mma_kernel,
                         cudaFuncAttributeMaxDynamicSharedMemorySize, AT_SMEM);

    // 1. Converts + RoPE table (one launch)
    prep_kernel<<<(PTOT + 255) / 256, 256>>>(x, qkv_w, out_w);

    // 2. QKV projection with fused bias+RoPE epilogue -> q/k/v fp16 [B,H,S,HD]
    gemm_mma_f16<1><<<dim3(NQKV / 128, Mc / 128), 256, GQ_SMEM>>>(
        x16, w16, qkv_b, nullptr, NQKV);

    // 3. Tensor-core flash attention (no-max softmax) -> ctx fp16
    attn_mma_kernel<<<dim3(Sc / 128, Bc * Hc), 256, AT_SMEM>>>(mask);

    // 4. Output projection -> fp32 out
    gemm_mma_f16<0><<<dim3(Ec / 128, Mc / 128), 256, GQ_SMEM>>>(
        c16, ow16, out_b, out, Ec);
}

// round 16
// speedup vs baseline: 1.0821x; 1.0593x over previous
#include <cuda_runtime.h>
#include <cuda_fp16.h>
#include <cstdint>
#include <cmath>

// Problem constants
constexpr int Bc  = 2;
constexpr int Sc  = 2048;
constexpr int Ec  = 1024;
constexpr int Hc  = 16;
constexpr int HDc = 64;
constexpr int Mc  = Bc * Sc;        // 4096 rows
constexpr int NQKV = 3 * Ec;        // 3072
constexpr int RHALF = 32;           // rotary pairs per head (ROT=64)
constexpr int GK = 1024;            // K dim of both projection GEMMs

// Scratch (static device globals; no allocation)
__device__ float g_cos[Sc * RHALF];
__device__ float g_sin[Sc * RHALF];

// fp16 buffers
__device__ __half g_x16[(size_t)Mc * Ec];
__device__ __half g_wqkv[(size_t)NQKV * Ec];
__device__ __half g_wout[(size_t)Ec * Ec];
__device__ __half g_ctx16[(size_t)Mc * Ec];

// q/k/v fp16 in [B,H,S,HD] layout (written directly by the QKV GEMM epilogue)
constexpr size_t QKV_ELEMS = (size_t)Bc * Hc * Sc * HDc;
__device__ __half g_q16[QKV_ELEMS];
__device__ __half g_k16[QKV_ELEMS];
__device__ __half g_v16[QKV_ELEMS];

// ---------------------------------------------------------------------------
// Portable (compute_103-safe) tensor-core helpers
// ---------------------------------------------------------------------------
__device__ __forceinline__ uint32_t smem_to_u32(const void* p) {
    uint32_t a;
    asm("{ .reg .u64 t; cvta.to.shared.u64 t, %1; cvt.u32.u64 %0, t; }"
        : "=r"(a) : "l"(p));
    return a;
}
__device__ __forceinline__ void cp16(uint32_t dst, const void* src) {
    asm volatile("cp.async.cg.shared.global [%0], [%1], 16;"
                 :: "r"(dst), "l"(src));
}
__device__ __forceinline__ void cp_commit() {
    asm volatile("cp.async.commit_group;" ::: "memory");
}
__device__ __forceinline__ void ldsm_x4(uint4& r, uint32_t addr) {
    asm volatile("ldmatrix.sync.aligned.m8n8.x4.shared.b16 {%0,%1,%2,%3}, [%4];"
                 : "=r"(r.x), "=r"(r.y), "=r"(r.z), "=r"(r.w) : "r"(addr));
}
__device__ __forceinline__ void ldsm_x4t(uint4& r, uint32_t addr) {
    asm volatile("ldmatrix.sync.aligned.m8n8.x4.trans.shared.b16 {%0,%1,%2,%3}, [%4];"
                 : "=r"(r.x), "=r"(r.y), "=r"(r.z), "=r"(r.w) : "r"(addr));
}
__device__ __forceinline__ void mmah(float* d, const uint4& a, uint32_t b0, uint32_t b1) {
    asm volatile(
        "mma.sync.aligned.m16n8k16.row.col.f32.f16.f16.f32 "
        "{%0,%1,%2,%3}, {%4,%5,%6,%7}, {%8,%9}, {%0,%1,%2,%3};"
        : "+f"(d[0]), "+f"(d[1]), "+f"(d[2]), "+f"(d[3])
        : "r"(a.x), "r"(a.y), "r"(a.z), "r"(a.w), "r"(b0), "r"(b1));
}
__device__ __forceinline__ float ex2f(float x) {
    float r; asm("ex2.approx.f32 %0, %1;" : "=f"(r) : "f"(x)); return r;
}
__device__ __forceinline__ uint32_t packh(float lo, float hi) {
    __half2 t = __floats2half2_rn(lo, hi);
    return *(uint32_t*)&t;
}

// ---------------------------------------------------------------------------
// Prep: fp32->fp16 converts for x / qkv_w / out_w + RoPE table, one launch.
// ---------------------------------------------------------------------------
constexpr int PN1 = Mc * Ec / 4;        // 262144
constexpr int PN2 = NQKV * Ec / 4;      // 786432
constexpr int PN3 = Ec * Ec / 4;        // 262144
constexpr int PTOT = PN1 + PN2 + PN3;   // 1310720

__global__ void prep_kernel(const float* __restrict__ x,
                            const float* __restrict__ qkv_w,
                            const float* __restrict__ out_w) {
    int idx = blockIdx.x * blockDim.x + threadIdx.x;

    if (idx < Sc * RHALF) {
        int s = idx / RHALF;
        int i = idx % RHALF;
        double inv_freq = exp(-(double)(2 * i) / 64.0 * log(10000.0));
        double ang = (double)s * inv_freq;
        g_cos[idx] = (float)cos(ang);
        g_sin[idx] = (float)sin(ang);
    }
    if (idx >= PTOT) return;

    const float* src;
    uint2* dp;
    int i4;
    if (idx < PN1)            { src = x;     dp = (uint2*)g_x16;  i4 = idx; }
    else if (idx < PN1 + PN2) { src = qkv_w; dp = (uint2*)g_wqkv; i4 = idx - PN1; }
    else                      { src = out_w; dp = (uint2*)g_wout; i4 = idx - PN1 - PN2; }

    float4 v = ((const float4*)src)[i4];
    uint2 o;
    o.x = packh(v.x, v.y);
    o.y = packh(v.z, v.w);
    dp[i4] = o;
}

// ---------------------------------------------------------------------------
// Warp-mma fp16 GEMM (round-11/13/15 proven config): 128x128 CTA tile, BK=64,
// 3-stage cp.async, 2 CTAs/SM, 8 warps (64x32 each). K=1024 -> 16 chunks.
// B fragments loaded as n-tile PAIRS via ldmatrix.x4.
// MODE 0: C fp32 = A@B^T + bias (out projection)
// MODE 1: QKV epilogue — bias + RoPE, write q/k/v fp16 in [B,H,S,HD].
// ---------------------------------------------------------------------------
constexpr int GQ_PITCH = 144;
constexpr int GQ_TILE  = 128 * GQ_PITCH;        // 18432
constexpr int GQ_B     = GQ_TILE;
constexpr int GQ_STAGE = 2 * GQ_TILE;           // 36864
constexpr int GQ_SMEM  = 3 * GQ_STAGE;          // 110592

template <int MODE>
__global__ __launch_bounds__(256, 2) void gemm_mma_f16(
    const __half* __restrict__ A16, const __half* __restrict__ B16,
    const float* __restrict__ bias, float* __restrict__ C, int Ndim)
{
    extern __shared__ char smg[];
    const uint32_t sb = smem_to_u32(smg);
    const int tid = threadIdx.x;
    const int lane = tid & 31;
    const int wid = tid >> 5;
    const int rowBase = blockIdx.y * 128;
    const int colBase = blockIdx.x * 128;
    const int wm = (wid >> 2) * 64;
    const int wn = (wid & 3) * 32;

    float acc[4][4][4];
#pragma unroll
    for (int mi = 0; mi < 4; mi++)
#pragma unroll
        for (int ni = 0; ni < 4; ni++)
#pragma unroll
            for (int e = 0; e < 4; e++) acc[mi][ni][e] = 0.f;

    auto issue = [&](int k) {
        const int k0 = k * 64;
        const uint32_t dst = sb + (uint32_t)(k % 3) * GQ_STAGE;
#pragma unroll
        for (int u = 0; u < 4; u++) {
            int lin = u * 256 + tid;
            int r = lin >> 3, seg = lin & 7;
            uint32_t so = r * GQ_PITCH + seg * 16;
            cp16(dst + so, A16 + (size_t)(rowBase + r) * GK + k0 + seg * 8);
            cp16(dst + GQ_B + so, B16 + (size_t)(colBase + r) * GK + k0 + seg * 8);
        }
        cp_commit();
    };

    issue(0);
    issue(1);
    for (int k = 0; k < 16; k++) {
        if (k < 15) asm volatile("cp.async.wait_group 1;" ::: "memory");
        else        asm volatile("cp.async.wait_group 0;" ::: "memory");
        __syncthreads();
        if (k + 2 < 16) issue(k + 2);   // stage (k+2)%3 — not read now or next

        const uint32_t St = sb + (uint32_t)(k % 3) * GQ_STAGE;
#pragma unroll
        for (int ks = 0; ks < 4; ks++) {
            uint4 a[4];
            uint4 bb[2];
            const uint32_t aro = (wm + (lane & 15)) * GQ_PITCH
                               + (ks * 16 + (lane >> 4) * 8) * 2;
#pragma unroll
            for (int mi = 0; mi < 4; mi++)
                ldsm_x4(a[mi], St + aro + mi * 16 * GQ_PITCH);
            const uint32_t bro = (wn + (lane & 7) + (lane >> 4) * 8) * GQ_PITCH
                               + (ks * 16 + ((lane >> 3) & 1) * 8) * 2;
#pragma unroll
            for (int nj = 0; nj < 2; nj++)
                ldsm_x4(bb[nj], St + GQ_B + bro + nj * 16 * GQ_PITCH);
#pragma unroll
            for (int mi = 0; mi < 4; mi++) {
                mmah(acc[mi][0], a[mi], bb[0].x, bb[0].y);
                mmah(acc[mi][1], a[mi], bb[0].z, bb[0].w);
                mmah(acc[mi][2], a[mi], bb[1].x, bb[1].y);
                mmah(acc[mi][3], a[mi], bb[1].z, bb[1].w);
            }
        }
    }

#pragma unroll
    for (int mi = 0; mi < 4; mi++) {
#pragma unroll
        for (int ni = 0; ni < 4; ni++) {
            int r0 = rowBase + wm + mi * 16 + (lane >> 2);
            int col = colBase + wn + ni * 8 + (lane & 3) * 2;
            float b0 = bias[col], b1 = bias[col + 1];
            float v00 = acc[mi][ni][0] + b0, v01 = acc[mi][ni][1] + b1;   // row r0
            float v10 = acc[mi][ni][2] + b0, v11 = acc[mi][ni][3] + b1;   // row r0+8

            if (MODE == 0) {
                *(float2*)&C[(size_t)r0 * Ndim + col] = make_float2(v00, v01);
                *(float2*)&C[(size_t)(r0 + 8) * Ndim + col] = make_float2(v10, v11);
            } else {
                int seg = col >> 10;             // 0=q 1=k 2=v
                int h = (col >> 6) & 15;
                int d = col & 63;
                int i = d >> 1;
                __half* dstBuf = (seg == 0) ? g_q16 : (seg == 1) ? g_k16 : g_v16;
#pragma unroll
                for (int rr = 0; rr < 2; rr++) {
                    int r = r0 + rr * 8;
                    float va = rr ? v10 : v00;
                    float vb = rr ? v11 : v01;
                    int bb2 = r >> 11;
                    int s = r & 2047;
                    size_t dst = (((size_t)(bb2 * Hc + h)) * Sc + s) * HDc + d;
                    if (seg == 2) {
                        *(__half2*)&dstBuf[dst] = __floats2half2_rn(va, vb);
                    } else {
                        float c  = g_cos[s * RHALF + i];
                        float sn = g_sin[s * RHALF + i];
                        *(__half2*)&dstBuf[dst] =
                            __floats2half2_rn(va * c - vb * sn, vb * c + va * sn);
                    }
                }
            }
        }
    }
}

// ---------------------------------------------------------------------------
// Tensor-core flash attention: fp16 operands, fp32 accum, no-max softmax,
// 2-buffer KV ring — per-warp structure identical to round 13/15, but
// 64 q-rows/CTA with 4 warps (128 threads) -> 1024 CTAs, finer wave grain.
// smem 46.6 KB, __launch_bounds__(128,4) -> 4 CTAs/SM (16 warps).
// ---------------------------------------------------------------------------
constexpr int AT_PITCH = 144;
constexpr int AT_Q   = 0;
constexpr int AT_KV  = 64 * AT_PITCH;             // 9216 (Q tile size)
constexpr int AT_V   = 64 * AT_PITCH;             // V offset within buffer
constexpr int AT_KVBUF = 2 * 64 * AT_PITCH;       // 18432 per buffer
constexpr int AT_MSK = AT_KV + 2 * AT_KVBUF;      // 46080
constexpr int AT_SMEM = AT_MSK + 2 * 64 * 4;      // 46592

__global__ __launch_bounds__(128, 4) void attn_mma_kernel(const int* __restrict__ mask)
{
    extern __shared__ char smA[];
    const uint32_t sb = smem_to_u32(smA);
    float* smask = (float*)(smA + AT_MSK);

    const int tid = threadIdx.x;
    const int lane = tid & 31;
    const int wid = tid >> 5;          // 0..3
    const int bh = blockIdx.y;
    const int b = bh >> 4, h = bh & 15;
    const int q0 = blockIdx.x * 64;

    const size_t base = (size_t)bh * Sc * HDc;
    const __half* Qg = g_q16 + base + (size_t)q0 * HDc;
    const __half* Kg = g_k16 + base;
    const __half* Vg = g_v16 + base;
    const int* mg = mask + b * Sc;

    // Q tile (64 rows) -> smem: 512 cp16 over 128 threads
#pragma unroll
    for (int u = 0; u < 4; u++) {
        int lin = u * 128 + tid;
        int r = lin >> 3, seg = lin & 7;
        cp16(sb + AT_Q + r * AT_PITCH + seg * 16, Qg + (size_t)r * HDc + seg * 8);
    }

    auto issueKV = [&](int it) {
        const uint32_t dst = sb + AT_KV + (uint32_t)(it & 1) * AT_KVBUF;
        const size_t koff = (size_t)it * 64 * HDc;
#pragma unroll
        for (int u = 0; u < 4; u++) {
            int lin = u * 128 + tid;
            int r = lin >> 3, seg = lin & 7;
            size_t off = koff + (size_t)r * HDc + seg * 8;
            uint32_t so = r * AT_PITCH + seg * 16;
            cp16(dst + so, Kg + off);
            cp16(dst + AT_V + so, Vg + off);
        }
        if (tid < 64) smask[(it & 1) * 64 + tid] = mg[it * 64 + tid] ? 0.f : -1e30f;
        cp_commit();
    };

    issueKV(0);
    issueKV(1);
    asm volatile("cp.async.wait_group 1;" ::: "memory");
    __syncthreads();

    uint4 qf[4];
#pragma unroll
    for (int ks = 0; ks < 4; ks++) {
        uint32_t ro = (wid * 16 + (lane & 15)) * AT_PITCH + (ks * 16 + (lane >> 4) * 8) * 2;
        ldsm_x4(qf[ks], sb + AT_Q + ro);
    }

    float accO[8][4];
#pragma unroll
    for (int nd = 0; nd < 8; nd++)
#pragma unroll
        for (int e = 0; e < 4; e++) accO[nd][e] = 0.f;
    float l0 = 0.f, l1 = 0.f;
    const float SC2 = 0.125f * 1.4426950408889634f;   // scale * log2(e)

    for (int it = 0; it < 32; it++) {
        if (it > 0) {
            if (it == 31) asm volatile("cp.async.wait_group 0;" ::: "memory");
            else          asm volatile("cp.async.wait_group 1;" ::: "memory");
            __syncthreads();
        }
        const uint32_t Kb = sb + AT_KV + (uint32_t)(it & 1) * AT_KVBUF;
        const int mbuf = (it & 1) * 64;

        // ---- S = Q K^T (key-tile pairs via ldsm_x4) ----
        float s[8][4];
#pragma unroll
        for (int ni = 0; ni < 8; ni++)
#pragma unroll
            for (int e = 0; e < 4; e++) s[ni][e] = 0.f;
#pragma unroll
        for (int ks = 0; ks < 4; ks++) {
            uint4 bk[4];
            uint32_t ro = ((lane & 7) + (lane >> 4) * 8) * AT_PITCH
                        + (ks * 16 + ((lane >> 3) & 1) * 8) * 2;
#pragma unroll
            for (int nj = 0; nj < 4; nj++)
                ldsm_x4(bk[nj], Kb + ro + nj * 16 * AT_PITCH);
#pragma unroll
            for (int nj = 0; nj < 4; nj++) {
                mmah(s[2 * nj],     qf[ks], bk[nj].x, bk[nj].y);
                mmah(s[2 * nj + 1], qf[ks], bk[nj].z, bk[nj].w);
            }
        }

        // ---- p = ex2(s*SC2 + mask), thread-local l accumulation ----
#pragma unroll
        for (int ni = 0; ni < 8; ni++) {
            float mb0 = smask[mbuf + ni * 8 + (lane & 3) * 2];
            float mb1 = smask[mbuf + ni * 8 + (lane & 3) * 2 + 1];
            s[ni][0] = ex2f(fmaf(s[ni][0], SC2, mb0));
            s[ni][1] = ex2f(fmaf(s[ni][1], SC2, mb1));
            s[ni][2] = ex2f(fmaf(s[ni][2], SC2, mb0));
            s[ni][3] = ex2f(fmaf(s[ni][3], SC2, mb1));
            l0 += s[ni][0] + s[ni][1];
            l1 += s[ni][2] + s[ni][3];
        }

        // ---- P fragments (fp16) from S accumulators ----
        uint4 ap[4];
#pragma unroll
        for (int ks2 = 0; ks2 < 4; ks2++) {
            const float* p0 = s[2 * ks2];
            const float* p1 = s[2 * ks2 + 1];
            ap[ks2].x = packh(p0[0], p0[1]);
            ap[ks2].y = packh(p0[2], p0[3]);
            ap[ks2].z = packh(p1[0], p1[1]);
            ap[ks2].w = packh(p1[2], p1[3]);
        }

        // ---- O += P V (d-tile pairs via ldsm_x4.trans) ----
#pragma unroll
        for (int ks2 = 0; ks2 < 4; ks2++) {
            uint4 bv[4];
            uint32_t rbase = (ks2 * 16 + (lane & 15)) * AT_PITCH + (lane >> 4) * 16;
#pragma unroll
            for (int nd2 = 0; nd2 < 4; nd2++)
                ldsm_x4t(bv[nd2], Kb + AT_V + rbase + nd2 * 32);
#pragma unroll
            for (int nd2 = 0; nd2 < 4; nd2++) {
                mmah(accO[2 * nd2],     ap[ks2], bv[nd2].x, bv[nd2].y);
                mmah(accO[2 * nd2 + 1], ap[ks2], bv[nd2].z, bv[nd2].w);
            }
        }

        __syncthreads();
        if (it + 2 < 32) issueKV(it + 2);
    }

    // ---- one-time row-sum reduction (quad lanes share a row) ----
    l0 += __shfl_xor_sync(0xffffffffu, l0, 1);
    l0 += __shfl_xor_sync(0xffffffffu, l0, 2);
    l1 += __shfl_xor_sync(0xffffffffu, l1, 1);
    l1 += __shfl_xor_sync(0xffffffffu, l1, 2);

    float inv0 = 1.f / l0, inv1 = 1.f / l1;
    int r0 = q0 + wid * 16 + (lane >> 2);
    int colb = h * HDc + (lane & 3) * 2;
#pragma unroll
    for (int nd = 0; nd < 8; nd++) {
        float c00 = accO[nd][0] * inv0, c01 = accO[nd][1] * inv0;
        float c10 = accO[nd][2] * inv1, c11 = accO[nd][3] * inv1;
        size_t i0 = (size_t)(b * Sc + r0) * Ec + colb + nd * 8;
        size_t i1 = (size_t)(b * Sc + r0 + 8) * Ec + colb + nd * 8;
        *(__half2*)&g_ctx16[i0] = __floats2half2_rn(c00, c01);
        *(__half2*)&g_ctx16[i1] = __floats2half2_rn(c10, c11);
    }
}

// ---------------------------------------------------------------------------
extern "C" void kernel_launch(void* const* d_in, const int* in_sizes, int n_in,
                              void* d_out, int out_size)
{
    const float* x     = (const float*)d_in[0];
    const int*   mask  = (const int*)d_in[1];
    const float* qkv_w = (const float*)d_in[2];
    const float* qkv_b = (const float*)d_in[3];
    const float* out_w = (const float*)d_in[4];
    const float* out_b = (const float*)d_in[5];
    float* out = (float*)d_out;

    __half *x16, *w16, *ow16, *c16;
    cudaGetSymbolAddress((void**)&x16,  g_x16);
    cudaGetSymbolAddress((void**)&w16,  g_wqkv);
    cudaGetSymbolAddress((void**)&ow16, g_wout);
    cudaGetSymbolAddress((void**)&c16,  g_ctx16);

    cudaFuncSetAttribute(gemm_mma_f16<0>,
                         cudaFuncAttributeMaxDynamicSharedMemorySize, GQ_SMEM);
    cudaFuncSetAttribute(gemm_mma_f16<1>,
                         cudaFuncAttributeMaxDynamicSharedMemorySize, GQ_SMEM);
    cudaFuncSetAttribute(attn_mma_kernel,
                         cudaFuncAttributeMaxDynamicSharedMemorySize, AT_SMEM);

    // 1. Converts + RoPE table (one launch)
    prep_kernel<<<(PTOT + 255) / 256, 256>>>(x, qkv_w, out_w);

    // 2. QKV projection with fused bias+RoPE epilogue -> q/k/v fp16 [B,H,S,HD]
    gemm_mma_f16<1><<<dim3(NQKV / 128, Mc / 128), 256, GQ_SMEM>>>(
        x16, w16, qkv_b, nullptr, NQKV);

    // 3. Tensor-core flash attention (no-max softmax, 64-row CTAs) -> ctx fp16
    attn_mma_kernel<<<dim3(Sc / 64, Bc * Hc), 128, AT_SMEM>>>(mask);

    // 4. Output projection -> fp32 out
    gemm_mma_f16<0><<<dim3(Ec / 128, Mc / 128), 256, GQ_SMEM>>>(
        c16, ow16, out_b, out, Ec);
}

// round 17
// speedup vs baseline: 1.0886x; 1.0060x over previous
#include <cuda_runtime.h>
#include <cuda_fp16.h>
#include <cstdint>
#include <cmath>

// Problem constants
constexpr int Bc  = 2;
constexpr int Sc  = 2048;
constexpr int Ec  = 1024;
constexpr int Hc  = 16;
constexpr int HDc = 64;
constexpr int Mc  = Bc * Sc;        // 4096 rows
constexpr int NQKV = 3 * Ec;        // 3072
constexpr int RHALF = 32;           // rotary pairs per head (ROT=64)
constexpr int GK = 1024;            // K dim of both projection GEMMs

// Scratch (static device globals; no allocation)
__device__ float g_cos[Sc * RHALF];
__device__ float g_sin[Sc * RHALF];

// fp16 buffers
__device__ __half g_x16[(size_t)Mc * Ec];
__device__ __half g_wqkv[(size_t)NQKV * Ec];
__device__ __half g_wout[(size_t)Ec * Ec];
__device__ __half g_ctx16[(size_t)Mc * Ec];

// q/k/v fp16 in [B,H,S,HD] layout (written directly by the QKV GEMM epilogue)
constexpr size_t QKV_ELEMS = (size_t)Bc * Hc * Sc * HDc;
__device__ __half g_q16[QKV_ELEMS];
__device__ __half g_k16[QKV_ELEMS];
__device__ __half g_v16[QKV_ELEMS];

// ---------------------------------------------------------------------------
// Portable (compute_103-safe) tensor-core helpers
// ---------------------------------------------------------------------------
__device__ __forceinline__ uint32_t smem_to_u32(const void* p) {
    uint32_t a;
    asm("{ .reg .u64 t; cvta.to.shared.u64 t, %1; cvt.u32.u64 %0, t; }"
        : "=r"(a) : "l"(p));
    return a;
}
__device__ __forceinline__ void cp16(uint32_t dst, const void* src) {
    asm volatile("cp.async.cg.shared.global [%0], [%1], 16;"
                 :: "r"(dst), "l"(src));
}
__device__ __forceinline__ void cp_commit() {
    asm volatile("cp.async.commit_group;" ::: "memory");
}
__device__ __forceinline__ void ldsm_x4(uint4& r, uint32_t addr) {
    asm volatile("ldmatrix.sync.aligned.m8n8.x4.shared.b16 {%0,%1,%2,%3}, [%4];"
                 : "=r"(r.x), "=r"(r.y), "=r"(r.z), "=r"(r.w) : "r"(addr));
}
__device__ __forceinline__ void ldsm_x4t(uint4& r, uint32_t addr) {
    asm volatile("ldmatrix.sync.aligned.m8n8.x4.trans.shared.b16 {%0,%1,%2,%3}, [%4];"
                 : "=r"(r.x), "=r"(r.y), "=r"(r.z), "=r"(r.w) : "r"(addr));
}
__device__ __forceinline__ void mmah(float* d, const uint4& a, uint32_t b0, uint32_t b1) {
    asm volatile(
        "mma.sync.aligned.m16n8k16.row.col.f32.f16.f16.f32 "
        "{%0,%1,%2,%3}, {%4,%5,%6,%7}, {%8,%9}, {%0,%1,%2,%3};"
        : "+f"(d[0]), "+f"(d[1]), "+f"(d[2]), "+f"(d[3])
        : "r"(a.x), "r"(a.y), "r"(a.z), "r"(a.w), "r"(b0), "r"(b1));
}
__device__ __forceinline__ float ex2f(float x) {
    float r; asm("ex2.approx.f32 %0, %1;" : "=f"(r) : "f"(x)); return r;
}
__device__ __forceinline__ uint32_t packh(float lo, float hi) {
    __half2 t = __floats2half2_rn(lo, hi);
    return *(uint32_t*)&t;
}

// ---------------------------------------------------------------------------
// Prep: fp32->fp16 converts for x / qkv_w / out_w + RoPE table, one launch.
// ---------------------------------------------------------------------------
constexpr int PN1 = Mc * Ec / 4;        // 262144
constexpr int PN2 = NQKV * Ec / 4;      // 786432
constexpr int PN3 = Ec * Ec / 4;        // 262144
constexpr int PTOT = PN1 + PN2 + PN3;   // 1310720

__global__ void prep_kernel(const float* __restrict__ x,
                            const float* __restrict__ qkv_w,
                            const float* __restrict__ out_w) {
    int idx = blockIdx.x * blockDim.x + threadIdx.x;

    if (idx < Sc * RHALF) {
        int s = idx / RHALF;
        int i = idx % RHALF;
        double inv_freq = exp(-(double)(2 * i) / 64.0 * log(10000.0));
        double ang = (double)s * inv_freq;
        g_cos[idx] = (float)cos(ang);
        g_sin[idx] = (float)sin(ang);
    }
    if (idx >= PTOT) return;

    const float* src;
    uint2* dp;
    int i4;
    if (idx < PN1)            { src = x;     dp = (uint2*)g_x16;  i4 = idx; }
    else if (idx < PN1 + PN2) { src = qkv_w; dp = (uint2*)g_wqkv; i4 = idx - PN1; }
    else                      { src = out_w; dp = (uint2*)g_wout; i4 = idx - PN1 - PN2; }

    float4 v = ((const float4*)src)[i4];
    uint2 o;
    o.x = packh(v.x, v.y);
    o.y = packh(v.z, v.w);
    dp[i4] = o;
}

// ---------------------------------------------------------------------------
// Warp-mma fp16 GEMM, fine-grain: 64x128 CTA tile, 4 warps (each the proven
// 64x32 warp tile / fragment maps), BK=64, 2-stage cp.async, 4 CTAs/SM.
// K=1024 -> 16 chunks. Stage = A(64 rows)|B(128 rows) x144B = 27.6 KB.
// Round-7-proven 2-stage ordering: issue(k+1) BEFORE wait(k), trailing sync.
// MODE 0: C fp32 = A@B^T + bias (out projection)
// MODE 1: QKV epilogue — bias + RoPE, write q/k/v fp16 in [B,H,S,HD].
// ---------------------------------------------------------------------------
constexpr int GQ_PITCH = 144;
constexpr int GQ_B     = 64 * GQ_PITCH;         // 9216  (B tile offset)
constexpr int GQ_STAGE = 192 * GQ_PITCH;        // 27648
constexpr int GQ_SMEM  = 2 * GQ_STAGE;          // 55296

template <int MODE>
__global__ __launch_bounds__(128, 4) void gemm_mma_f16(
    const __half* __restrict__ A16, const __half* __restrict__ B16,
    const float* __restrict__ bias, float* __restrict__ C, int Ndim)
{
    extern __shared__ char smg[];
    const uint32_t sb = smem_to_u32(smg);
    const int tid = threadIdx.x;
    const int lane = tid & 31;
    const int wid = tid >> 5;          // 0..3
    const int rowBase = blockIdx.y * 64;
    const int colBase = blockIdx.x * 128;
    const int wn = wid * 32;           // warp n offset; all warps share M rows

    float acc[4][4][4];
#pragma unroll
    for (int mi = 0; mi < 4; mi++)
#pragma unroll
        for (int ni = 0; ni < 4; ni++)
#pragma unroll
            for (int e = 0; e < 4; e++) acc[mi][ni][e] = 0.f;

    // load chunk k (A 64x64, B 128x64 fp16) into stage k&1
    auto issue = [&](int k) {
        const int k0 = k * 64;
        const uint32_t dst = sb + (uint32_t)(k & 1) * GQ_STAGE;
#pragma unroll
        for (int u = 0; u < 4; u++) {           // A: 64 rows x 8 segs = 512
            int lin = u * 128 + tid;
            int r = lin >> 3, seg = lin & 7;
            cp16(dst + r * GQ_PITCH + seg * 16,
                 A16 + (size_t)(rowBase + r) * GK + k0 + seg * 8);
        }
#pragma unroll
        for (int u = 0; u < 8; u++) {           // B: 128 rows x 8 segs = 1024
            int lin = u * 128 + tid;
            int r = lin >> 3, seg = lin & 7;
            cp16(dst + GQ_B + r * GQ_PITCH + seg * 16,
                 B16 + (size_t)(colBase + r) * GK + k0 + seg * 8);
        }
        cp_commit();
    };

    issue(0);
    for (int k = 0; k < 16; k++) {
        if (k + 1 < 16) {
            issue(k + 1);                                   // writes stage (k+1)&1
            asm volatile("cp.async.wait_group 1;" ::: "memory");
        } else {
            asm volatile("cp.async.wait_group 0;" ::: "memory");
        }
        __syncthreads();

        const uint32_t St = sb + (uint32_t)(k & 1) * GQ_STAGE;
#pragma unroll
        for (int ks = 0; ks < 4; ks++) {
            uint4 a[4];
            uint4 bb[2];
            const uint32_t aro = (lane & 15) * GQ_PITCH
                               + (ks * 16 + (lane >> 4) * 8) * 2;
#pragma unroll
            for (int mi = 0; mi < 4; mi++)
                ldsm_x4(a[mi], St + aro + mi * 16 * GQ_PITCH);
            // B: two n8-tiles per ldsm_x4 (lanes 16-31 address the +8 n-tile)
            const uint32_t bro = (wn + (lane & 7) + (lane >> 4) * 8) * GQ_PITCH
                               + (ks * 16 + ((lane >> 3) & 1) * 8) * 2;
#pragma unroll
            for (int nj = 0; nj < 2; nj++)
                ldsm_x4(bb[nj], St + GQ_B + bro + nj * 16 * GQ_PITCH);
#pragma unroll
            for (int mi = 0; mi < 4; mi++) {
                mmah(acc[mi][0], a[mi], bb[0].x, bb[0].y);
                mmah(acc[mi][1], a[mi], bb[0].z, bb[0].w);
                mmah(acc[mi][2], a[mi], bb[1].x, bb[1].y);
                mmah(acc[mi][3], a[mi], bb[1].z, bb[1].w);
            }
        }
        __syncthreads();   // stage k&1 consumed before issue(k+2) reuses it
    }

#pragma unroll
    for (int mi = 0; mi < 4; mi++) {
#pragma unroll
        for (int ni = 0; ni < 4; ni++) {
            int r0 = rowBase + mi * 16 + (lane >> 2);
            int col = colBase + wn + ni * 8 + (lane & 3) * 2;
            float b0 = bias[col], b1 = bias[col + 1];
            float v00 = acc[mi][ni][0] + b0, v01 = acc[mi][ni][1] + b1;   // row r0
            float v10 = acc[mi][ni][2] + b0, v11 = acc[mi][ni][3] + b1;   // row r0+8

            if (MODE == 0) {
                *(float2*)&C[(size_t)r0 * Ndim + col] = make_float2(v00, v01);
                *(float2*)&C[(size_t)(r0 + 8) * Ndim + col] = make_float2(v10, v11);
            } else {
                int seg = col >> 10;             // 0=q 1=k 2=v
                int h = (col >> 6) & 15;
                int d = col & 63;
                int i = d >> 1;
                __half* dstBuf = (seg == 0) ? g_q16 : (seg == 1) ? g_k16 : g_v16;
#pragma unroll
                for (int rr = 0; rr < 2; rr++) {
                    int r = r0 + rr * 8;
                    float va = rr ? v10 : v00;
                    float vb = rr ? v11 : v01;
                    int bb2 = r >> 11;
                    int s = r & 2047;
                    size_t dst = (((size_t)(bb2 * Hc + h)) * Sc + s) * HDc + d;
                    if (seg == 2) {
                        *(__half2*)&dstBuf[dst] = __floats2half2_rn(va, vb);
                    } else {
                        float c  = g_cos[s * RHALF + i];
                        float sn = g_sin[s * RHALF + i];
                        *(__half2*)&dstBuf[dst] =
                            __floats2half2_rn(va * c - vb * sn, vb * c + va * sn);
                    }
                }
            }
        }
    }
}

// ---------------------------------------------------------------------------
// Tensor-core flash attention (round-16 banked best): fp16, fp32 accum,
// no-max softmax, 2-buffer KV ring, 64 q-rows/CTA, 4 warps, 4 CTAs/SM.
// ---------------------------------------------------------------------------
constexpr int AT_PITCH = 144;
constexpr int AT_Q   = 0;
constexpr int AT_KV  = 64 * AT_PITCH;             // 9216 (Q tile size)
constexpr int AT_V   = 64 * AT_PITCH;             // V offset within buffer
constexpr int AT_KVBUF = 2 * 64 * AT_PITCH;       // 18432 per buffer
constexpr int AT_MSK = AT_KV + 2 * AT_KVBUF;      // 46080
constexpr int AT_SMEM = AT_MSK + 2 * 64 * 4;      // 46592

__global__ __launch_bounds__(128, 4) void attn_mma_kernel(const int* __restrict__ mask)
{
    extern __shared__ char smA[];
    const uint32_t sb = smem_to_u32(smA);
    float* smask = (float*)(smA + AT_MSK);

    const int tid = threadIdx.x;
    const int lane = tid & 31;
    const int wid = tid >> 5;          // 0..3
    const int bh = blockIdx.y;
    const int b = bh >> 4, h = bh & 15;
    const int q0 = blockIdx.x * 64;

    const size_t base = (size_t)bh * Sc * HDc;
    const __half* Qg = g_q16 + base + (size_t)q0 * HDc;
    const __half* Kg = g_k16 + base;
    const __half* Vg = g_v16 + base;
    const int* mg = mask + b * Sc;

#pragma unroll
    for (int u = 0; u < 4; u++) {
        int lin = u * 128 + tid;
        int r = lin >> 3, seg = lin & 7;
        cp16(sb + AT_Q + r * AT_PITCH + seg * 16, Qg + (size_t)r * HDc + seg * 8);
    }

    auto issueKV = [&](int it) {
        const uint32_t dst = sb + AT_KV + (uint32_t)(it & 1) * AT_KVBUF;
        const size_t koff = (size_t)it * 64 * HDc;
#pragma unroll
        for (int u = 0; u < 4; u++) {
            int lin = u * 128 + tid;
            int r = lin >> 3, seg = lin & 7;
            size_t off = koff + (size_t)r * HDc + seg * 8;
            uint32_t so = r * AT_PITCH + seg * 16;
            cp16(dst + so, Kg + off);
            cp16(dst + AT_V + so, Vg + off);
        }
        if (tid < 64) smask[(it & 1) * 64 + tid] = mg[it * 64 + tid] ? 0.f : -1e30f;
        cp_commit();
    };

    issueKV(0);
    issueKV(1);
    asm volatile("cp.async.wait_group 1;" ::: "memory");
    __syncthreads();

    uint4 qf[4];
#pragma unroll
    for (int ks = 0; ks < 4; ks++) {
        uint32_t ro = (wid * 16 + (lane & 15)) * AT_PITCH + (ks * 16 + (lane >> 4) * 8) * 2;
        ldsm_x4(qf[ks], sb + AT_Q + ro);
    }

    float accO[8][4];
#pragma unroll
    for (int nd = 0; nd < 8; nd++)
#pragma unroll
        for (int e = 0; e < 4; e++) accO[nd][e] = 0.f;
    float l0 = 0.f, l1 = 0.f;
    const float SC2 = 0.125f * 1.4426950408889634f;   // scale * log2(e)

    for (int it = 0; it < 32; it++) {
        if (it > 0) {
            if (it == 31) asm volatile("cp.async.wait_group 0;" ::: "memory");
            else          asm volatile("cp.async.wait_group 1;" ::: "memory");
            __syncthreads();
        }
        const uint32_t Kb = sb + AT_KV + (uint32_t)(it & 1) * AT_KVBUF;
        const int mbuf = (it & 1) * 64;

        // ---- S = Q K^T (key-tile pairs via ldsm_x4) ----
        float s[8][4];
#pragma unroll
        for (int ni = 0; ni < 8; ni++)
#pragma unroll
            for (int e = 0; e < 4; e++) s[ni][e] = 0.f;
#pragma unroll
        for (int ks = 0; ks < 4; ks++) {
            uint4 bk[4];
            uint32_t ro = ((lane & 7) + (lane >> 4) * 8) * AT_PITCH
                        + (ks * 16 + ((lane >> 3) & 1) * 8) * 2;
#pragma unroll
            for (int nj = 0; nj < 4; nj++)
                ldsm_x4(bk[nj], Kb + ro + nj * 16 * AT_PITCH);
#pragma unroll
            for (int nj = 0; nj < 4; nj++) {
                mmah(s[2 * nj],     qf[ks], bk[nj].x, bk[nj].y);
                mmah(s[2 * nj + 1], qf[ks], bk[nj].z, bk[nj].w);
            }
        }

        // ---- p = ex2(s*SC2 + mask), thread-local l accumulation ----
#pragma unroll
        for (int ni = 0; ni < 8; ni++) {
            float mb0 = smask[mbuf + ni * 8 + (lane & 3) * 2];
            float mb1 = smask[mbuf + ni * 8 + (lane & 3) * 2 + 1];
            s[ni][0] = ex2f(fmaf(s[ni][0], SC2, mb0));
            s[ni][1] = ex2f(fmaf(s[ni][1], SC2, mb1));
            s[ni][2] = ex2f(fmaf(s[ni][2], SC2, mb0));
            s[ni][3] = ex2f(fmaf(s[ni][3], SC2, mb1));
            l0 += s[ni][0] + s[ni][1];
            l1 += s[ni][2] + s[ni][3];
        }

        // ---- P fragments (fp16) from S accumulators ----
        uint4 ap[4];
#pragma unroll
        for (int ks2 = 0; ks2 < 4; ks2++) {
            const float* p0 = s[2 * ks2];
            const float* p1 = s[2 * ks2 + 1];
            ap[ks2].x = packh(p0[0], p0[1]);
            ap[ks2].y = packh(p0[2], p0[3]);
            ap[ks2].z = packh(p1[0], p1[1]);
            ap[ks2].w = packh(p1[2], p1[3]);
        }

        // ---- O += P V (d-tile pairs via ldsm_x4.trans) ----
#pragma unroll
        for (int ks2 = 0; ks2 < 4; ks2++) {
            uint4 bv[4];
            uint32_t rbase = (ks2 * 16 + (lane & 15)) * AT_PITCH + (lane >> 4) * 16;
#pragma unroll
            for (int nd2 = 0; nd2 < 4; nd2++)
                ldsm_x4t(bv[nd2], Kb + AT_V + rbase + nd2 * 32);
#pragma unroll
            for (int nd2 = 0; nd2 < 4; nd2++) {
                mmah(accO[2 * nd2],     ap[ks2], bv[nd2].x, bv[nd2].y);
                mmah(accO[2 * nd2 + 1], ap[ks2], bv[nd2].z, bv[nd2].w);
            }
        }

        __syncthreads();
        if (it + 2 < 32) issueKV(it + 2);
    }

    // ---- one-time row-sum reduction (quad lanes share a row) ----
    l0 += __shfl_xor_sync(0xffffffffu, l0, 1);
    l0 += __shfl_xor_sync(0xffffffffu, l0, 2);
    l1 += __shfl_xor_sync(0xffffffffu, l1, 1);
    l1 += __shfl_xor_sync(0xffffffffu, l1, 2);

    float inv0 = 1.f / l0, inv1 = 1.f / l1;
    int r0 = q0 + wid * 16 + (lane >> 2);
    int colb = h * HDc + (lane & 3) * 2;
#pragma unroll
    for (int nd = 0; nd < 8; nd++) {
        float c00 = accO[nd][0] * inv0, c01 = accO[nd][1] * inv0;
        float c10 = accO[nd][2] * inv1, c11 = accO[nd][3] * inv1;
        size_t i0 = (size_t)(b * Sc + r0) * Ec + colb + nd * 8;
        size_t i1 = (size_t)(b * Sc + r0 + 8) * Ec + colb + nd * 8;
        *(__half2*)&g_ctx16[i0] = __floats2half2_rn(c00, c01);
        *(__half2*)&g_ctx16[i1] = __floats2half2_rn(c10, c11);
    }
}

// ---------------------------------------------------------------------------
extern "C" void kernel_launch(void* const* d_in, const int* in_sizes, int n_in,
                              void* d_out, int out_size)
{
    const float* x     = (const float*)d_in[0];
    const int*   mask  = (const int*)d_in[1];
    const float* qkv_w = (const float*)d_in[2];
    const float* qkv_b = (const float*)d_in[3];
    const float* out_w = (const float*)d_in[4];
    const float* out_b = (const float*)d_in[5];
    float* out = (float*)d_out;

    __half *x16, *w16, *ow16, *c16;
    cudaGetSymbolAddress((void**)&x16,  g_x16);
    cudaGetSymbolAddress((void**)&w16,  g_wqkv);
    cudaGetSymbolAddress((void**)&ow16, g_wout);
    cudaGetSymbolAddress((void**)&c16,  g_ctx16);

    cudaFuncSetAttribute(gemm_mma_f16<0>,
                         cudaFuncAttributeMaxDynamicSharedMemorySize, GQ_SMEM);
    cudaFuncSetAttribute(gemm_mma_f16<1>,
                         cudaFuncAttributeMaxDynamicSharedMemorySize, GQ_SMEM);
    cudaFuncSetAttribute(attn_mma_kernel,
                         cudaFuncAttributeMaxDynamicSharedMemorySize, AT_SMEM);

    // 1. Converts + RoPE table (one launch)
    prep_kernel<<<(PTOT + 255) / 256, 256>>>(x, qkv_w, out_w);

    // 2. QKV projection with fused bias+RoPE epilogue -> q/k/v fp16 [B,H,S,HD]
    gemm_mma_f16<1><<<dim3(NQKV / 128, Mc / 64), 128, GQ_SMEM>>>(
        x16, w16, qkv_b, nullptr, NQKV);

    // 3. Tensor-core flash attention (no-max softmax, 64-row CTAs) -> ctx fp16
    attn_mma_kernel<<<dim3(Sc / 64, Bc * Hc), 128, AT_SMEM>>>(mask);

    // 4. Output projection -> fp32 out
    gemm_mma_f16<0><<<dim3(Ec / 128, Mc / 64), 128, GQ_SMEM>>>(
        c16, ow16, out_b, out, Ec);
}